// round 16
// baseline (speedup 1.0000x reference)
#include <cuda_runtime.h>
#include <cuda_bf16.h>
#include <cstdint>

#define KCODES 512
#define DDIM 64
#define HW 4096
#define MPTS 262144
#define ZQ_ELEMS 16777216
#define TPB 256                  // 8 warps; 2 m-tiles per warp (R14 topology)
#define NTILES (MPTS / TPB)      // 1024 tiles of 256 points
#define NPERS 296                // persistent CTAs (148 SMs * 2)

// smem layout (bytes)
#define SM_ESQ 0                 // 512 f32        [0,2048)
#define SM_T1 2048               // 256 f32        [2048,3072)
#define SM_T2 3072               // 256 f32        [3072,4096)
#define SM_T3 4096               // 256 f32        [4096,5120)
#define SM_A 5120                // 256 rows * 128B bf16 z tile [5120,37888)
#define SM_B 37888               // 512 rows * 128B bf16 codebook [37888,103424)
#define SM_TILE 103424           // tile ticket broadcast (u32)
#define SM_TOTAL 103552          // ~101.1 KB -> 2 CTAs/SM

#define TAU 1.0e-3f

__device__ double g_loss_sum;
__device__ unsigned g_ctr;
__device__ unsigned g_ticket;
__device__ float g_esq[KCODES];
__device__ __align__(16) __nv_bfloat16 g_embbf[KCODES * DDIM];

// ---- prep: e_sq (exact sequential fp32) + bf16 codebook ----
__global__ void vq_prep(const float* __restrict__ emb) {
    int k = threadIdx.x;                     // 512 threads
    const float* row = emb + k * DDIM;
    float q = 0.f;
    #pragma unroll
    for (int d = 0; d < DDIM; d++) {
        float v = row[d];
        q = __fadd_rn(q, __fmul_rn(v, v));
        g_embbf[k * DDIM + d] = __float2bfloat16(v);
    }
    g_esq[k] = q;
    if (k == 0) { g_loss_sum = 0.0; g_ctr = 0u; g_ticket = 0u; }
}

// ---- helpers ----
__device__ __forceinline__ uint32_t smem_u32(const void* p) {
    uint32_t a;
    asm("{ .reg .u64 t; cvta.to.shared.u64 t, %1; cvt.u32.u64 %0, t; }"
        : "=r"(a) : "l"(p));
    return a;
}
__device__ __forceinline__ uint32_t bf16x2(float a, float b) {  // lo=a, hi=b
    uint32_t r;
    asm("cvt.rn.bf16x2.f32 %0, %1, %2;" : "=r"(r) : "f"(b), "f"(a));
    return r;
}
__device__ __forceinline__ void ldsm_x4(uint32_t addr, uint32_t& r0, uint32_t& r1,
                                        uint32_t& r2, uint32_t& r3) {
    asm volatile("ldmatrix.sync.aligned.m8n8.x4.shared.b16 {%0,%1,%2,%3}, [%4];"
                 : "=r"(r0), "=r"(r1), "=r"(r2), "=r"(r3) : "r"(addr));
}
__device__ __forceinline__ void mma_bf16(float& d0, float& d1, float& d2, float& d3,
                                         uint32_t a0, uint32_t a1, uint32_t a2, uint32_t a3,
                                         uint32_t b0, uint32_t b1) {
    asm volatile(
        "mma.sync.aligned.m16n8k16.row.col.f32.bf16.bf16.f32 "
        "{%0,%1,%2,%3}, {%4,%5,%6,%7}, {%8,%9}, {%0,%1,%2,%3};"
        : "+f"(d0), "+f"(d1), "+f"(d2), "+f"(d3)
        : "r"(a0), "r"(a1), "r"(a2), "r"(a3), "r"(b0), "r"(b1));
}
__device__ __forceinline__ float exact_dist(float S, float esq, float dot) {
    return __fsub_rn(__fadd_rn(S, esq), __fmul_rn(2.0f, dot));
}
// index payload in low 9 mantissa bits (|delta| <= ~2e-6 for |s| <= 0.25)
__device__ __forceinline__ float paylo(float s, int k) {
    return __uint_as_float((__float_as_uint(s) & 0xFFFFFE00u) | (uint32_t)k);
}
// insert sp into exact sorted top-3 (m1 <= m2 <= m3)
__device__ __forceinline__ void top3_ins(float& m1, float& m2, float& m3, float sp) {
    float t1 = fminf(m1, sp);
    float u1 = fmaxf(m1, sp);
    float t2 = fminf(m2, u1);
    float u2 = fmaxf(m2, u1);
    m3 = fminf(m3, u2);
    m1 = t1; m2 = t2;
}
// exact merge of two sorted triples -> 3 smallest of union
__device__ __forceinline__ void top3_mrg(float& m1, float& m2, float& m3,
                                         float a1, float a2, float a3) {
    float s1 = fminf(m1, a1), l1 = fmaxf(m1, a1);
    float s2 = fminf(m2, a2), l2 = fmaxf(m2, a2);
    float s3 = fminf(m3, a3);
    m1 = s1;
    m2 = fminf(l1, s2);
    m3 = fminf(fmaxf(l1, s2), fminf(l2, s3));
}

__global__ __launch_bounds__(TPB, 2)
void vq_main(const float* __restrict__ z, const float* __restrict__ emb,
             float* __restrict__ out) {
    extern __shared__ char smem[];
    const uint32_t sb = smem_u32(smem);
    const int tid = threadIdx.x;
    const int lane = tid & 31, wid = tid >> 5;
    const int g = lane >> 2, t = lane & 3;
    const int wbase = wid * 32;

    float* sm_esq = (float*)(smem + SM_ESQ);
    float* sm_t1 = (float*)(smem + SM_T1);
    float* sm_t2 = (float*)(smem + SM_T2);
    float* sm_t3 = (float*)(smem + SM_T3);
    volatile unsigned* sm_tile = (volatile unsigned*)(smem + SM_TILE);

    // One-time: e_sq + B tile (codebook) into smem
    for (int i = tid; i < KCODES; i += TPB) sm_esq[i] = g_esq[i];
    {
        const uint4* gb = (const uint4*)g_embbf;
        #pragma unroll 4
        for (int it = 0; it < 16; it++) {
            uint32_t i16 = (uint32_t)(it * TPB + tid);
            uint4 v = gb[i16];
            uint32_t row = i16 >> 3, j = i16 & 7;
            uint32_t a = sb + SM_B + row * 128 + ((j ^ (row & 7)) << 4);
            asm volatile("st.shared.v4.b32 [%0], {%1,%2,%3,%4};"
                         :: "r"(a), "r"(v.x), "r"(v.y), "r"(v.z), "r"(v.w) : "memory");
        }
    }

    const int brow = lane & 7;
    const int bsub = lane >> 3;
    const float INF = __int_as_float(0x7f800000);
    double lsum_run = 0.0;

    for (;;) {
        if (tid == 0) *sm_tile = atomicAdd(&g_ticket, 1u);
        __syncthreads();       // also protects prev-tile smem reads vs overwrite
        const int tile = (int)*sm_tile;
        if (tile >= NTILES) break;

        const int p  = tile * TPB + tid;
        const int n  = p >> 12;
        const int hw = p & (HW - 1);
        const float* zp = z + (size_t)n * (DDIM * HW) + hw;

        // Phase A: stream z -> z_sq (sequential fp32) + bf16 A tile
        float S = 0.f;
        #pragma unroll
        for (int j = 0; j < 8; j++) {
            float v[8];
            #pragma unroll
            for (int e = 0; e < 8; e++) v[e] = zp[(8 * j + e) * HW];
            #pragma unroll
            for (int e = 0; e < 8; e++) S = __fadd_rn(S, __fmul_rn(v[e], v[e]));
            uint32_t w0 = bf16x2(v[0], v[1]);
            uint32_t w1 = bf16x2(v[2], v[3]);
            uint32_t w2 = bf16x2(v[4], v[5]);
            uint32_t w3 = bf16x2(v[6], v[7]);
            uint32_t a = sb + SM_A + (uint32_t)tid * 128 + (uint32_t)((j ^ (tid & 7)) << 4);
            asm volatile("st.shared.v4.b32 [%0], {%1,%2,%3,%4};"
                         :: "r"(a), "r"(w0), "r"(w1), "r"(w2), "r"(w3) : "memory");
        }
        __syncthreads();

        // A fragments: 2 m-tiles x 4 k-steps
        uint32_t afr[2][4][4];
        {
            const int sub = lane >> 3;
            const int rowo = (lane & 7) + ((sub & 1) << 3);
            #pragma unroll
            for (int m = 0; m < 2; m++) {
                #pragma unroll
                for (int kc = 0; kc < 4; kc++) {
                    int row = wbase + 16 * m + rowo;
                    int gran = 2 * kc + (sub >> 1);
                    uint32_t a = sb + SM_A + (uint32_t)row * 128
                               + (uint32_t)((gran ^ (row & 7)) << 4);
                    ldsm_x4(a, afr[m][kc][0], afr[m][kc][1], afr[m][kc][2], afr[m][kc][3]);
                }
            }
        }

        // SINGLE MMA sweep: exact top-3 of payloaded scores per fragment row
        // rows per thread: r0 = wbase+g (m0 lo), r1 = wbase+8+g (m0 hi),
        //                  r2 = wbase+16+g (m1 lo), r3 = wbase+24+g (m1 hi)
        float T1[4], T2[4], T3[4];
        #pragma unroll
        for (int r = 0; r < 4; r++) { T1[r] = INF; T2[r] = INF; T3[r] = INF; }
        #pragma unroll 2
        for (int nt = 0; nt < 64; nt++) {
            uint32_t b[8];
            #pragma unroll
            for (int kk = 0; kk < 2; kk++) {
                int row = nt * 8 + brow;
                int gran = 4 * kk + bsub;
                uint32_t a = sb + SM_B + (uint32_t)row * 128
                           + (uint32_t)((gran ^ (row & 7)) << 4);
                ldsm_x4(a, b[4*kk], b[4*kk+1], b[4*kk+2], b[4*kk+3]);
            }
            float2 e2 = *(const float2*)(sm_esq + nt * 8 + 2 * t);
            const int kb = nt * 8 + 2 * t;
            #pragma unroll
            for (int m = 0; m < 2; m++) {
                float dA0 = 0.f, dA1 = 0.f, dA2 = 0.f, dA3 = 0.f;
                float dB0 = 0.f, dB1 = 0.f, dB2 = 0.f, dB3 = 0.f;
                mma_bf16(dA0, dA1, dA2, dA3, afr[m][0][0], afr[m][0][1], afr[m][0][2], afr[m][0][3], b[0], b[1]);
                mma_bf16(dB0, dB1, dB2, dB3, afr[m][1][0], afr[m][1][1], afr[m][1][2], afr[m][1][3], b[2], b[3]);
                mma_bf16(dA0, dA1, dA2, dA3, afr[m][2][0], afr[m][2][1], afr[m][2][2], afr[m][2][3], b[4], b[5]);
                mma_bf16(dB0, dB1, dB2, dB3, afr[m][3][0], afr[m][3][1], afr[m][3][2], afr[m][3][3], b[6], b[7]);
                float s0 = fmaf(-2.f, dA0 + dB0, e2.x);
                float s1 = fmaf(-2.f, dA1 + dB1, e2.y);
                float s2 = fmaf(-2.f, dA2 + dB2, e2.x);
                float s3 = fmaf(-2.f, dA3 + dB3, e2.y);
                const int rL = 2 * m, rH = 2 * m + 1;
                top3_ins(T1[rL], T2[rL], T3[rL], paylo(s0, kb));
                top3_ins(T1[rL], T2[rL], T3[rL], paylo(s1, kb + 1));
                top3_ins(T1[rH], T2[rH], T3[rH], paylo(s2, kb));
                top3_ins(T1[rH], T2[rH], T3[rH], paylo(s3, kb + 1));
            }
        }
        // quad reduce (exact 3-way merges)
        #pragma unroll
        for (int off = 1; off <= 2; off <<= 1) {
            #pragma unroll
            for (int r = 0; r < 4; r++) {
                float a1 = __shfl_xor_sync(0xffffffffu, T1[r], off);
                float a2 = __shfl_xor_sync(0xffffffffu, T2[r], off);
                float a3 = __shfl_xor_sync(0xffffffffu, T3[r], off);
                top3_mrg(T1[r], T2[r], T3[r], a1, a2, a3);
            }
        }
        if (t == 0) {
            #pragma unroll
            for (int m = 0; m < 2; m++) {
                int rlo = wbase + 16 * m + g, rhi = rlo + 8;
                sm_t1[rlo] = T1[2*m];   sm_t2[rlo] = T2[2*m];   sm_t3[rlo] = T3[2*m];
                sm_t1[rhi] = T1[2*m+1]; sm_t2[rhi] = T2[2*m+1]; sm_t3[rhi] = T3[2*m+1];
            }
        }
        __syncthreads();

        // Epilogue: decide bestk per point
        const float m1 = sm_t1[tid], m2 = sm_t2[tid], m3 = sm_t3[tid];
        const int k1 = (int)(__float_as_uint(m1) & 511u);
        int bestk;
        if (m2 - m1 > TAU) {
            bestk = k1;                                // unique candidate, certain
        } else if (m3 - m1 > TAU) {
            // exact argmin in {k1, k2}: exact rescore, reference tie-break
            int k2 = (int)(__float_as_uint(m2) & 511u);
            int ka = min(k1, k2), kc = max(k1, k2);
            const float* ea = emb + ka * DDIM;
            const float* ec = emb + kc * DDIM;
            float dota = 0.f, dotc = 0.f;
            #pragma unroll 2
            for (int j = 0; j < 8; j++) {
                float zc[8];
                #pragma unroll
                for (int e = 0; e < 8; e++) zc[e] = zp[(8 * j + e) * HW];
                #pragma unroll
                for (int e = 0; e < 8; e++) {
                    dota = __fmaf_rn(zc[e], ea[8 * j + e], dota);
                    dotc = __fmaf_rn(zc[e], ec[8 * j + e], dotc);
                }
            }
            float da = exact_dist(S, sm_esq[ka], dota);
            float dc = exact_dist(S, sm_esq[kc], dotc);
            bestk = (dc < da) ? kc : ka;               // ascending-k strict <
        } else {
            // rare: exact full scan, ascending k, strict <
            float bestd = INF; bestk = 0;
            for (int k0 = 0; k0 < KCODES; k0 += 8) {
                float dot[8];
                #pragma unroll
                for (int c = 0; c < 8; c++) dot[c] = 0.f;
                #pragma unroll 1
                for (int j = 0; j < 8; j++) {
                    float zc[8];
                    #pragma unroll
                    for (int e = 0; e < 8; e++) zc[e] = zp[(8 * j + e) * HW];
                    #pragma unroll
                    for (int c = 0; c < 8; c++) {
                        const float* er = emb + (k0 + c) * DDIM + 8 * j;
                        #pragma unroll
                        for (int e = 0; e < 8; e++)
                            dot[c] = __fmaf_rn(zc[e], er[e], dot[c]);
                    }
                }
                #pragma unroll
                for (int c = 0; c < 8; c++) {
                    float dist = exact_dist(S, sm_esq[k0 + c], dot[c]);
                    if (dist < bestd) { bestd = dist; bestk = k0 + c; }
                }
            }
        }

        // Output pass: z_q (straight-through), fp32 loss, index
        const float* er = emb + bestk * DDIM;
        float* outz = out + (size_t)n * (DDIM * HW) + hw;
        float lsum = 0.f;
        #pragma unroll 2
        for (int j = 0; j < 8; j++) {
            float zc[8], ec[8];
            #pragma unroll
            for (int e = 0; e < 8; e++) zc[e] = zp[(8 * j + e) * HW];
            #pragma unroll
            for (int e = 0; e < 8; e++) ec[e] = er[8 * j + e];
            #pragma unroll
            for (int e = 0; e < 8; e++) {
                float v = zc[e], q = ec[e];
                outz[(8 * j + e) * HW] = __fadd_rn(v, __fsub_rn(q, v)); // fl(z + fl(zq - z))
                float x = __fsub_rn(v, q);
                lsum = __fmaf_rn(x, x, lsum);
            }
        }
        out[ZQ_ELEMS + 1 + p] = (float)bestk;
        lsum_run += (double)lsum;
    }

    // loss: warp-reduce per-thread running sums, one atomic per warp
    #pragma unroll
    for (int off = 16; off > 0; off >>= 1)
        lsum_run += __shfl_down_sync(0xffffffffu, lsum_run, off);
    if (lane == 0) atomicAdd(&g_loss_sum, lsum_run);

    __threadfence();
    __syncthreads();
    if (tid == 0) {
        unsigned tk = atomicAdd(&g_ctr, 1u);
        if (tk == (unsigned)(NPERS - 1)) {
            double s = atomicAdd(&g_loss_sum, 0.0);
            out[ZQ_ELEMS] = (float)(s / (double)ZQ_ELEMS);
        }
    }
}

extern "C" void kernel_launch(void* const* d_in, const int* in_sizes, int n_in,
                              void* d_out, int out_size) {
    const float* z   = (const float*)d_in[0];   // z_e (64,64,64,64) f32
    const float* emb = (const float*)d_in[1];   // emb_weight (512,64) f32
    float* out = (float*)d_out;

    cudaFuncSetAttribute(vq_main, cudaFuncAttributeMaxDynamicSharedMemorySize, SM_TOTAL);
    vq_prep<<<1, KCODES>>>(emb);
    vq_main<<<NPERS, TPB, SM_TOTAL>>>(z, emb, out);
}

// round 17
// speedup vs baseline: 1.1882x; 1.1882x over previous
#include <cuda_runtime.h>
#include <cuda_bf16.h>
#include <cstdint>

#define KCODES 512
#define DDIM 64
#define HW 4096
#define MPTS 262144
#define ZQ_ELEMS 16777216
#define TPB 256                  // 8 warps; 2 m-tiles per warp
#define NTILES (MPTS / TPB)      // 1024 tiles of 256 points
#define NPERS 296                // persistent CTAs (148 SMs * 2)

// smem layout (bytes)
#define SM_ESQ 0                 // 512 f32        [0,2048)
#define SM_T1 2048               // 256 f32
#define SM_T2 3072               // 256 f32
#define SM_T3 4096               // 256 f32
#define SM_S 5120                // 256 f32 (z_sq per point)
#define SM_Q 6144                // 256 u32 (queue of rows needing full scan)
#define SM_BK 7168               // 256 u32 (full-scan results)
#define SM_QN 8192               // u32 queue count
#define SM_A 8320                // 256 rows * 128B bf16 z tile [8320,41088)
#define SM_B 41088               // 512 rows * 128B bf16 codebook [41088,106624)
#define SM_TILE 106624           // tile ticket broadcast (u32)
#define SM_TOTAL 106752          // ~104.3 KB -> 2 CTAs/SM

#define TAU 1.0e-3f

__device__ double g_loss_sum;
__device__ unsigned g_ctr;
__device__ unsigned g_ticket;
__device__ float g_esq[KCODES];
__device__ __align__(16) __nv_bfloat16 g_embbf[KCODES * DDIM];

// ---- prep: e_sq (exact sequential fp32) + bf16 codebook ----
__global__ void vq_prep(const float* __restrict__ emb) {
    int k = threadIdx.x;                     // 512 threads
    const float* row = emb + k * DDIM;
    float q = 0.f;
    #pragma unroll
    for (int d = 0; d < DDIM; d++) {
        float v = row[d];
        q = __fadd_rn(q, __fmul_rn(v, v));
        g_embbf[k * DDIM + d] = __float2bfloat16(v);
    }
    g_esq[k] = q;
    if (k == 0) { g_loss_sum = 0.0; g_ctr = 0u; g_ticket = 0u; }
}

// ---- helpers ----
__device__ __forceinline__ uint32_t smem_u32(const void* p) {
    uint32_t a;
    asm("{ .reg .u64 t; cvta.to.shared.u64 t, %1; cvt.u32.u64 %0, t; }"
        : "=r"(a) : "l"(p));
    return a;
}
__device__ __forceinline__ uint32_t bf16x2(float a, float b) {  // lo=a, hi=b
    uint32_t r;
    asm("cvt.rn.bf16x2.f32 %0, %1, %2;" : "=r"(r) : "f"(b), "f"(a));
    return r;
}
__device__ __forceinline__ void ldsm_x4(uint32_t addr, uint32_t& r0, uint32_t& r1,
                                        uint32_t& r2, uint32_t& r3) {
    asm volatile("ldmatrix.sync.aligned.m8n8.x4.shared.b16 {%0,%1,%2,%3}, [%4];"
                 : "=r"(r0), "=r"(r1), "=r"(r2), "=r"(r3) : "r"(addr));
}
__device__ __forceinline__ void mma_bf16(float& d0, float& d1, float& d2, float& d3,
                                         uint32_t a0, uint32_t a1, uint32_t a2, uint32_t a3,
                                         uint32_t b0, uint32_t b1) {
    asm volatile(
        "mma.sync.aligned.m16n8k16.row.col.f32.bf16.bf16.f32 "
        "{%0,%1,%2,%3}, {%4,%5,%6,%7}, {%8,%9}, {%0,%1,%2,%3};"
        : "+f"(d0), "+f"(d1), "+f"(d2), "+f"(d3)
        : "r"(a0), "r"(a1), "r"(a2), "r"(a3), "r"(b0), "r"(b1));
}
__device__ __forceinline__ float exact_dist(float S, float esq, float dot) {
    return __fsub_rn(__fadd_rn(S, esq), __fmul_rn(2.0f, dot));
}
// index payload in low 9 mantissa bits (|delta| <= ~8e-6 for |s| <= 0.25)
__device__ __forceinline__ float paylo(float s, int k) {
    return __uint_as_float((__float_as_uint(s) & 0xFFFFFE00u) | (uint32_t)k);
}
__device__ __forceinline__ void top3_ins(float& m1, float& m2, float& m3, float sp) {
    float t1 = fminf(m1, sp);
    float u1 = fmaxf(m1, sp);
    float t2 = fminf(m2, u1);
    float u2 = fmaxf(m2, u1);
    m3 = fminf(m3, u2);
    m1 = t1; m2 = t2;
}
__device__ __forceinline__ void top3_mrg(float& m1, float& m2, float& m3,
                                         float a1, float a2, float a3) {
    float s1 = fminf(m1, a1), l1 = fmaxf(m1, a1);
    float s2 = fminf(m2, a2), l2 = fmaxf(m2, a2);
    float s3 = fminf(m3, a3);
    m1 = s1;
    m2 = fminf(l1, s2);
    m3 = fminf(fmaxf(l1, s2), fminf(l2, s3));
}

__global__ __launch_bounds__(TPB, 2)
void vq_main(const float* __restrict__ z, const float* __restrict__ emb,
             float* __restrict__ out) {
    extern __shared__ char smem[];
    const uint32_t sb = smem_u32(smem);
    const int tid = threadIdx.x;
    const int lane = tid & 31, wid = tid >> 5;
    const int g = lane >> 2, t = lane & 3;
    const int wbase = wid * 32;

    float* sm_esq = (float*)(smem + SM_ESQ);
    float* sm_t1 = (float*)(smem + SM_T1);
    float* sm_t2 = (float*)(smem + SM_T2);
    float* sm_t3 = (float*)(smem + SM_T3);
    float* sm_S = (float*)(smem + SM_S);
    unsigned* sm_q = (unsigned*)(smem + SM_Q);
    unsigned* sm_bk = (unsigned*)(smem + SM_BK);
    unsigned* sm_qn = (unsigned*)(smem + SM_QN);
    volatile unsigned* sm_tile = (volatile unsigned*)(smem + SM_TILE);

    // One-time: e_sq + B tile (codebook) into smem
    for (int i = tid; i < KCODES; i += TPB) sm_esq[i] = g_esq[i];
    {
        const uint4* gb = (const uint4*)g_embbf;
        #pragma unroll 4
        for (int it = 0; it < 16; it++) {
            uint32_t i16 = (uint32_t)(it * TPB + tid);
            uint4 v = gb[i16];
            uint32_t row = i16 >> 3, j = i16 & 7;
            uint32_t a = sb + SM_B + row * 128 + ((j ^ (row & 7)) << 4);
            asm volatile("st.shared.v4.b32 [%0], {%1,%2,%3,%4};"
                         :: "r"(a), "r"(v.x), "r"(v.y), "r"(v.z), "r"(v.w) : "memory");
        }
    }

    const int brow = lane & 7;
    const int bsub = lane >> 3;
    const float INF = __int_as_float(0x7f800000);
    double lsum_run = 0.0;

    for (;;) {
        if (tid == 0) { *sm_tile = atomicAdd(&g_ticket, 1u); *sm_qn = 0u; }
        __syncthreads();
        const int tile = (int)*sm_tile;
        if (tile >= NTILES) break;

        const int p  = tile * TPB + tid;
        const int n  = p >> 12;
        const int hw = p & (HW - 1);
        const float* zp = z + (size_t)n * (DDIM * HW) + hw;
        const float* zbase = z + (size_t)n * (DDIM * HW);
        const int hwbase = tile * TPB & (HW - 1);

        // Phase A: stream z -> z_sq (sequential fp32) + bf16 A tile
        float S = 0.f;
        #pragma unroll
        for (int j = 0; j < 8; j++) {
            float v[8];
            #pragma unroll
            for (int e = 0; e < 8; e++) v[e] = zp[(8 * j + e) * HW];
            #pragma unroll
            for (int e = 0; e < 8; e++) S = __fadd_rn(S, __fmul_rn(v[e], v[e]));
            uint32_t w0 = bf16x2(v[0], v[1]);
            uint32_t w1 = bf16x2(v[2], v[3]);
            uint32_t w2 = bf16x2(v[4], v[5]);
            uint32_t w3 = bf16x2(v[6], v[7]);
            uint32_t a = sb + SM_A + (uint32_t)tid * 128 + (uint32_t)((j ^ (tid & 7)) << 4);
            asm volatile("st.shared.v4.b32 [%0], {%1,%2,%3,%4};"
                         :: "r"(a), "r"(w0), "r"(w1), "r"(w2), "r"(w3) : "memory");
        }
        sm_S[tid] = S;
        __syncthreads();

        // A fragments: 2 m-tiles x 4 k-steps
        uint32_t afr[2][4][4];
        {
            const int sub = lane >> 3;
            const int rowo = (lane & 7) + ((sub & 1) << 3);
            #pragma unroll
            for (int m = 0; m < 2; m++) {
                #pragma unroll
                for (int kc = 0; kc < 4; kc++) {
                    int row = wbase + 16 * m + rowo;
                    int gran = 2 * kc + (sub >> 1);
                    uint32_t a = sb + SM_A + (uint32_t)row * 128
                               + (uint32_t)((gran ^ (row & 7)) << 4);
                    ldsm_x4(a, afr[m][kc][0], afr[m][kc][1], afr[m][kc][2], afr[m][kc][3]);
                }
            }
        }

        // SINGLE MMA sweep: exact top-3 of payloaded scores per fragment row
        float T1[4], T2[4], T3[4];
        #pragma unroll
        for (int r = 0; r < 4; r++) { T1[r] = INF; T2[r] = INF; T3[r] = INF; }
        #pragma unroll 2
        for (int nt = 0; nt < 64; nt++) {
            uint32_t b[8];
            #pragma unroll
            for (int kk = 0; kk < 2; kk++) {
                int row = nt * 8 + brow;
                int gran = 4 * kk + bsub;
                uint32_t a = sb + SM_B + (uint32_t)row * 128
                           + (uint32_t)((gran ^ (row & 7)) << 4);
                ldsm_x4(a, b[4*kk], b[4*kk+1], b[4*kk+2], b[4*kk+3]);
            }
            float2 e2 = *(const float2*)(sm_esq + nt * 8 + 2 * t);
            const int kb = nt * 8 + 2 * t;
            #pragma unroll
            for (int m = 0; m < 2; m++) {
                float dA0 = 0.f, dA1 = 0.f, dA2 = 0.f, dA3 = 0.f;
                float dB0 = 0.f, dB1 = 0.f, dB2 = 0.f, dB3 = 0.f;
                mma_bf16(dA0, dA1, dA2, dA3, afr[m][0][0], afr[m][0][1], afr[m][0][2], afr[m][0][3], b[0], b[1]);
                mma_bf16(dB0, dB1, dB2, dB3, afr[m][1][0], afr[m][1][1], afr[m][1][2], afr[m][1][3], b[2], b[3]);
                mma_bf16(dA0, dA1, dA2, dA3, afr[m][2][0], afr[m][2][1], afr[m][2][2], afr[m][2][3], b[4], b[5]);
                mma_bf16(dB0, dB1, dB2, dB3, afr[m][3][0], afr[m][3][1], afr[m][3][2], afr[m][3][3], b[6], b[7]);
                float s0 = fmaf(-2.f, dA0 + dB0, e2.x);
                float s1 = fmaf(-2.f, dA1 + dB1, e2.y);
                float s2 = fmaf(-2.f, dA2 + dB2, e2.x);
                float s3 = fmaf(-2.f, dA3 + dB3, e2.y);
                const int rL = 2 * m, rH = 2 * m + 1;
                top3_ins(T1[rL], T2[rL], T3[rL], paylo(s0, kb));
                top3_ins(T1[rL], T2[rL], T3[rL], paylo(s1, kb + 1));
                top3_ins(T1[rH], T2[rH], T3[rH], paylo(s2, kb));
                top3_ins(T1[rH], T2[rH], T3[rH], paylo(s3, kb + 1));
            }
        }
        #pragma unroll
        for (int off = 1; off <= 2; off <<= 1) {
            #pragma unroll
            for (int r = 0; r < 4; r++) {
                float a1 = __shfl_xor_sync(0xffffffffu, T1[r], off);
                float a2 = __shfl_xor_sync(0xffffffffu, T2[r], off);
                float a3 = __shfl_xor_sync(0xffffffffu, T3[r], off);
                top3_mrg(T1[r], T2[r], T3[r], a1, a2, a3);
            }
        }
        if (t == 0) {
            #pragma unroll
            for (int m = 0; m < 2; m++) {
                int rlo = wbase + 16 * m + g, rhi = rlo + 8;
                sm_t1[rlo] = T1[2*m];   sm_t2[rlo] = T2[2*m];   sm_t3[rlo] = T3[2*m];
                sm_t1[rhi] = T1[2*m+1]; sm_t2[rhi] = T2[2*m+1]; sm_t3[rhi] = T3[2*m+1];
            }
        }
        __syncthreads();

        // Per-point decision (fast / 2-candidate exact rescore / enqueue)
        const float m1 = sm_t1[tid], m2 = sm_t2[tid], m3 = sm_t3[tid];
        const int k1 = (int)(__float_as_uint(m1) & 511u);
        int bestk = -1;
        if (m2 - m1 > TAU) {
            bestk = k1;
        } else if (m3 - m1 > TAU) {
            int k2 = (int)(__float_as_uint(m2) & 511u);
            int ka = min(k1, k2), kc = max(k1, k2);
            const float* ea = emb + ka * DDIM;
            const float* ec = emb + kc * DDIM;
            float dota = 0.f, dotc = 0.f;
            #pragma unroll 2
            for (int j = 0; j < 8; j++) {
                float zc[8];
                #pragma unroll
                for (int e = 0; e < 8; e++) zc[e] = zp[(8 * j + e) * HW];
                #pragma unroll
                for (int e = 0; e < 8; e++) {
                    dota = __fmaf_rn(zc[e], ea[8 * j + e], dota);
                    dotc = __fmaf_rn(zc[e], ec[8 * j + e], dotc);
                }
            }
            float da = exact_dist(S, sm_esq[ka], dota);
            float dc = exact_dist(S, sm_esq[kc], dotc);
            bestk = (dc < da) ? kc : ka;
        } else {
            unsigned qi = atomicAdd(sm_qn, 1u);
            sm_q[qi] = (unsigned)tid;
        }
        __syncthreads();

        // Warp-cooperative exact full scans for queued points (rare)
        const int qn = (int)*sm_qn;
        for (int i = wid; i < qn; i += 8) {
            const int row = (int)sm_q[i];
            const float* zq = zbase + hwbase + row;
            const float Sq = sm_S[row];
            const int k0 = lane * 16;           // 16 ascending codes per lane
            float bd = INF; int bk = KCODES;
            #pragma unroll 1
            for (int h = 0; h < 2; h++) {       // two halves of 8 codes
                float dot[8];
                #pragma unroll
                for (int c = 0; c < 8; c++) dot[c] = 0.f;
                #pragma unroll 1
                for (int j = 0; j < 8; j++) {
                    float zc[8];
                    #pragma unroll
                    for (int e = 0; e < 8; e++) zc[e] = zq[(8 * j + e) * HW];
                    #pragma unroll
                    for (int c = 0; c < 8; c++) {
                        const float* er = emb + (k0 + 8 * h + c) * DDIM + 8 * j;
                        #pragma unroll
                        for (int e = 0; e < 8; e++)
                            dot[c] = __fmaf_rn(zc[e], er[e], dot[c]);
                    }
                }
                #pragma unroll
                for (int c = 0; c < 8; c++) {
                    float dist = exact_dist(Sq, sm_esq[k0 + 8 * h + c], dot[c]);
                    if (dist < bd) { bd = dist; bk = k0 + 8 * h + c; }  // ascending k
                }
            }
            // warp argmin with reference tie-break (lower k on exact equality)
            #pragma unroll
            for (int off = 16; off > 0; off >>= 1) {
                float od = __shfl_down_sync(0xffffffffu, bd, off);
                int ok = __shfl_down_sync(0xffffffffu, bk, off);
                if (od < bd || (od == bd && ok < bk)) { bd = od; bk = ok; }
            }
            if (lane == 0) sm_bk[row] = (unsigned)bk;
        }
        __syncthreads();
        if (bestk < 0) bestk = (int)sm_bk[tid];

        // Output pass: z_q (straight-through), fp32 loss, index
        const float* er = emb + bestk * DDIM;
        float* outz = out + (size_t)n * (DDIM * HW) + hw;
        float lsum = 0.f;
        #pragma unroll 2
        for (int j = 0; j < 8; j++) {
            float zc[8], ec[8];
            #pragma unroll
            for (int e = 0; e < 8; e++) zc[e] = zp[(8 * j + e) * HW];
            #pragma unroll
            for (int e = 0; e < 8; e++) ec[e] = er[8 * j + e];
            #pragma unroll
            for (int e = 0; e < 8; e++) {
                float v = zc[e], q = ec[e];
                outz[(8 * j + e) * HW] = __fadd_rn(v, __fsub_rn(q, v)); // fl(z + fl(zq - z))
                float x = __fsub_rn(v, q);
                lsum = __fmaf_rn(x, x, lsum);
            }
        }
        out[ZQ_ELEMS + 1 + p] = (float)bestk;
        lsum_run += (double)lsum;
    }

    // loss: warp-reduce per-thread running sums, one atomic per warp
    #pragma unroll
    for (int off = 16; off > 0; off >>= 1)
        lsum_run += __shfl_down_sync(0xffffffffu, lsum_run, off);
    if (lane == 0) atomicAdd(&g_loss_sum, lsum_run);

    __threadfence();
    __syncthreads();
    if (tid == 0) {
        unsigned tk = atomicAdd(&g_ctr, 1u);
        if (tk == (unsigned)(NPERS - 1)) {
            double s = atomicAdd(&g_loss_sum, 0.0);
            out[ZQ_ELEMS] = (float)(s / (double)ZQ_ELEMS);
        }
    }
}

extern "C" void kernel_launch(void* const* d_in, const int* in_sizes, int n_in,
                              void* d_out, int out_size) {
    const float* z   = (const float*)d_in[0];   // z_e (64,64,64,64) f32
    const float* emb = (const float*)d_in[1];   // emb_weight (512,64) f32
    float* out = (float*)d_out;

    cudaFuncSetAttribute(vq_main, cudaFuncAttributeMaxDynamicSharedMemorySize, SM_TOTAL);
    vq_prep<<<1, KCODES>>>(emb);
    vq_main<<<NPERS, TPB, SM_TOTAL>>>(z, emb, out);
}